// round 4
// baseline (speedup 1.0000x reference)
#include <cuda_runtime.h>
#include <math.h>

#define NN 50000
#define NE 200000
#define XLD 516      // xc row stride (max in_c)
#define ALD 1548     // aggr / wperm row stride (max 3*in_c)

// ---------------- scratch (no allocations allowed) ----------------
__device__ float g_xc[(size_t)NN * XLD];     // layer input  [N, in_c] (+concat cols)
__device__ float g_aggr[(size_t)NN * ALD];   // aggregated messages, k = h*in_c + i
__device__ float g_wperm[512 * ALD];         // wout permuted to k = h*in_c + i
__device__ int   g_cnt[NN];
__device__ int   g_rowptr[NN + 1];
__device__ int   g_cursor[NN];
__device__ int   g_src[NE];                  // src node per CSR slot
__device__ float g_ea[NE * 6];               // edge_attr per CSR slot
__device__ int   g_is64;

// ---------------- edge_index dtype detection (int64 vs int32) ----------------
__global__ void k_detect(const int* ei32) {
    if (threadIdx.x == 0 && blockIdx.x == 0) {
        int z = 1;
        for (int k = 0; k < 64; k++)
            if (ei32[2 * k + 1] != 0) { z = 0; break; }
        g_is64 = z;   // all high words zero -> values are int64 (nonneg < 2^31)
    }
}

__device__ __forceinline__ int eload(const void* ei, int pos) {
    if (g_is64) return (int)((const long long*)ei)[pos];
    return ((const int*)ei)[pos];
}

// ---------------- CSR construction ----------------
__global__ void k_zero() {
    int i = blockIdx.x * blockDim.x + threadIdx.x;
    if (i < NN) g_cnt[i] = 0;
}

__global__ void k_hist(const void* ei) {
    int e = blockIdx.x * blockDim.x + threadIdx.x;
    if (e < NE) atomicAdd(&g_cnt[eload(ei, NE + e)], 1);
}

__global__ void k_scan() {   // exclusive scan of g_cnt -> g_rowptr (single block, 1024 thr)
    __shared__ int sm[1024];
    __shared__ int carry;
    if (threadIdx.x == 0) carry = 0;
    __syncthreads();
    for (int base = 0; base < NN; base += 1024) {
        int idx = base + threadIdx.x;
        int v = (idx < NN) ? g_cnt[idx] : 0;
        sm[threadIdx.x] = v;
        __syncthreads();
#pragma unroll
        for (int off = 1; off < 1024; off <<= 1) {
            int t = (threadIdx.x >= off) ? sm[threadIdx.x - off] : 0;
            __syncthreads();
            sm[threadIdx.x] += t;
            __syncthreads();
        }
        if (idx < NN) g_rowptr[idx] = carry + sm[threadIdx.x] - v;
        __syncthreads();
        if (threadIdx.x == 1023) carry += sm[1023];
        __syncthreads();
    }
    if (threadIdx.x == 0) g_rowptr[NN] = carry;
}

__global__ void k_cursor() {
    int i = blockIdx.x * blockDim.x + threadIdx.x;
    if (i < NN) g_cursor[i] = g_rowptr[i];
}

__global__ void k_scatter(const void* ei, const float* __restrict__ ea) {
    int e = blockIdx.x * blockDim.x + threadIdx.x;
    if (e >= NE) return;
    int d = eload(ei, NE + e);
    int s = eload(ei, e);
    int pos = atomicAdd(&g_cursor[d], 1);
    g_src[pos] = s;
#pragma unroll
    for (int a = 0; a < 6; a++) g_ea[pos * 6 + a] = ea[e * 6 + a];
}

// ---------------- xc preparation / fixups ----------------
__global__ void k_prep(const float* __restrict__ x, const float* __restrict__ sdf,
                       const float* __restrict__ nat) {
    int n = blockIdx.x * blockDim.x + threadIdx.x;
    if (n >= NN) return;
    float* r = &g_xc[(size_t)n * XLD];
#pragma unroll
    for (int c = 0; c < 5; c++) r[c] = x[n * 5 + c];
    r[5] = sdf[n];
    r[6] = nat[n];
}

__global__ void k_setcol(int col, const float* __restrict__ src) {
    int n = blockIdx.x * blockDim.x + threadIdx.x;
    if (n < NN) g_xc[(size_t)n * XLD + col] = src[n];
}

__global__ void k_copyfy(const float* __restrict__ fy) {
    int idx = blockIdx.x * blockDim.x + threadIdx.x;
    if (idx >= NN * 3) return;
    int n = idx / 3, c = idx - n * 3;
    g_xc[(size_t)n * XLD + c] = fy[idx];
}

// ---------------- weight permutation: wperm[o, h*in_c+i] = wout[o, i*3+h] ----------------
__global__ void k_permw(const float* __restrict__ wout, int oc, int in_c) {
    int K = 3 * in_c;
    int idx = blockIdx.x * blockDim.x + threadIdx.x;
    if (idx >= oc * K) return;
    int o = idx / K, k = idx - o * K;
    int h = k / in_c, i = k - h * in_c;
    g_wperm[(size_t)o * ALD + k] = wout[(size_t)o * K + i * 3 + h];
}

// ---------------- fused scaling + gather + segment-sum ----------------
// Block handles 64 nodes; win/bin staged in SMEM once per block.
// aggr[n, h*in_c + i] = sum_{e -> n} relu(ea_e . win[i*3+h] + bin[i*3+h]) * xc[src_e, i]
__global__ void __launch_bounds__(256) k_aggr(int in_c, const float* __restrict__ win,
                                              const float* __restrict__ bin) {
    __shared__ float s_w[ALD * 6];   // 37.2 KB
    __shared__ float s_b[ALD];       //  6.2 KB
    int R = 3 * in_c;
    for (int t = threadIdx.x; t < R * 6; t += 256) s_w[t] = win[t];
    for (int t = threadIdx.x; t < R;     t += 256) s_b[t] = bin[t];
    __syncthreads();

    int n0 = blockIdx.x * 64;
    int nend = (n0 + 64 < NN) ? n0 + 64 : NN;
    for (int n = n0; n < nend; n++) {
        int rs = g_rowptr[n], re = g_rowptr[n + 1];
        for (int i = threadIdx.x; i < in_c; i += 256) {
            const float* w = &s_w[i * 18];
            float b0 = s_b[3 * i + 0], b1 = s_b[3 * i + 1], b2 = s_b[3 * i + 2];
            float a0 = 0.f, a1 = 0.f, a2 = 0.f;
            for (int j = rs; j < re; j++) {
                int s = g_src[j];
                float xv = __ldg(&g_xc[(size_t)s * XLD + i]);
                const float* eap = &g_ea[j * 6];
                float s0 = b0, s1 = b1, s2 = b2;
#pragma unroll
                for (int a = 0; a < 6; a++) {
                    float e = eap[a];
                    s0 = fmaf(e, w[a],      s0);
                    s1 = fmaf(e, w[6 + a],  s1);
                    s2 = fmaf(e, w[12 + a], s2);
                }
                a0 = fmaf(fmaxf(s0, 0.f), xv, a0);
                a1 = fmaf(fmaxf(s1, 0.f), xv, a1);
                a2 = fmaf(fmaxf(s2, 0.f), xv, a2);
            }
            float* d = &g_aggr[(size_t)n * ALD];
            d[i] = a0;
            d[in_c + i] = a1;
            d[2 * in_c + i] = a2;
        }
    }
}

// ---------------- fp32x2 helpers ----------------
__device__ __forceinline__ void fma2(unsigned long long& c, unsigned long long a,
                                     unsigned long long b) {
    asm("fma.rn.f32x2 %0, %1, %2, %0;" : "+l"(c) : "l"(a), "l"(b));
}
__device__ __forceinline__ unsigned long long bcast2(float x) {
    unsigned long long r;
    asm("mov.b64 %0, {%1, %1};" : "=l"(r) : "f"(x));
    return r;
}

__device__ __forceinline__ float4 g_ld4(const float* __restrict__ p, int rowok,
                                        size_t off, int gk, int K) {
    float4 v = make_float4(0.f, 0.f, 0.f, 0.f);
    if (rowok) {
        const float* q = p + off + gk;
        if (gk + 4 <= K) {
            v = *reinterpret_cast<const float4*>(q);
        } else {
            if (gk + 0 < K) v.x = q[0];
            if (gk + 1 < K) v.y = q[1];
            if (gk + 2 < K) v.z = q[2];
            if (gk + 3 < K) v.w = q[3];
        }
    }
    return v;
}

// ---------------- main GEMM: g_xc[m, coloff + n] = relu(tanh(aggr @ wperm^T + bias)) ----------------
// C = A[M,K] * B^T where B = g_wperm[512, K]. BM=BN=128, BK=16, 8x8/thread, FFMA2.
__global__ void __launch_bounds__(256) k_gemm(int M, int K,
                                              const float* __restrict__ bias, int coloff) {
    __shared__ float As[16][132];
    __shared__ float Bs[16][132];
    const int tid = threadIdx.x;
    const int tx = tid & 15;
    const int ty = tid >> 4;
    const int m0 = blockIdx.y * 128;
    const int n0 = blockIdx.x * 128;

    unsigned long long acc[8][4];
#pragma unroll
    for (int i = 0; i < 8; i++)
#pragma unroll
        for (int j = 0; j < 4; j++) acc[i][j] = 0ULL;

    const int li0 = tid * 2, li1 = tid * 2 + 1;
    const int row0 = li0 >> 2, kc0 = (li0 & 3) << 2;
    const int row1 = li1 >> 2, kc1 = (li1 & 3) << 2;

    const int ntiles = (K + 15) >> 4;
    float4 ra0, ra1, rb0, rb1;

    {
        const int kt = 0;
        ra0 = g_ld4(g_aggr, (m0 + row0) < M, (size_t)(m0 + row0) * ALD, kt + kc0, K);
        ra1 = g_ld4(g_aggr, (m0 + row1) < M, (size_t)(m0 + row1) * ALD, kt + kc1, K);
        rb0 = g_ld4(g_wperm, 1, (size_t)(n0 + row0) * ALD, kt + kc0, K);
        rb1 = g_ld4(g_wperm, 1, (size_t)(n0 + row1) * ALD, kt + kc1, K);
    }

    for (int t = 0; t < ntiles; t++) {
        As[kc0 + 0][row0] = ra0.x; As[kc0 + 1][row0] = ra0.y;
        As[kc0 + 2][row0] = ra0.z; As[kc0 + 3][row0] = ra0.w;
        As[kc1 + 0][row1] = ra1.x; As[kc1 + 1][row1] = ra1.y;
        As[kc1 + 2][row1] = ra1.z; As[kc1 + 3][row1] = ra1.w;
        Bs[kc0 + 0][row0] = rb0.x; Bs[kc0 + 1][row0] = rb0.y;
        Bs[kc0 + 2][row0] = rb0.z; Bs[kc0 + 3][row0] = rb0.w;
        Bs[kc1 + 0][row1] = rb1.x; Bs[kc1 + 1][row1] = rb1.y;
        Bs[kc1 + 2][row1] = rb1.z; Bs[kc1 + 3][row1] = rb1.w;
        __syncthreads();

        if (t + 1 < ntiles) {
            const int kt = (t + 1) << 4;
            ra0 = g_ld4(g_aggr, (m0 + row0) < M, (size_t)(m0 + row0) * ALD, kt + kc0, K);
            ra1 = g_ld4(g_aggr, (m0 + row1) < M, (size_t)(m0 + row1) * ALD, kt + kc1, K);
            rb0 = g_ld4(g_wperm, 1, (size_t)(n0 + row0) * ALD, kt + kc0, K);
            rb1 = g_ld4(g_wperm, 1, (size_t)(n0 + row1) * ALD, kt + kc1, K);
        }

#pragma unroll
        for (int k = 0; k < 16; k++) {
            float4 a0 = *reinterpret_cast<const float4*>(&As[k][ty * 8]);
            float4 a1 = *reinterpret_cast<const float4*>(&As[k][ty * 8 + 4]);
            unsigned long long bb[4];
            bb[0] = *reinterpret_cast<const unsigned long long*>(&Bs[k][tx * 8 + 0]);
            bb[1] = *reinterpret_cast<const unsigned long long*>(&Bs[k][tx * 8 + 2]);
            bb[2] = *reinterpret_cast<const unsigned long long*>(&Bs[k][tx * 8 + 4]);
            bb[3] = *reinterpret_cast<const unsigned long long*>(&Bs[k][tx * 8 + 6]);
            float am[8] = {a0.x, a0.y, a0.z, a0.w, a1.x, a1.y, a1.z, a1.w};
#pragma unroll
            for (int mi = 0; mi < 8; mi++) {
                unsigned long long aa = bcast2(am[mi]);
#pragma unroll
                for (int nj = 0; nj < 4; nj++) fma2(acc[mi][nj], aa, bb[nj]);
            }
        }
        __syncthreads();
    }

#pragma unroll
    for (int mi = 0; mi < 8; mi++) {
        int gm = m0 + ty * 8 + mi;
        if (gm >= M) continue;
        float* crow = &g_xc[(size_t)gm * XLD + coloff];
#pragma unroll
        for (int nj = 0; nj < 4; nj++) {
            int cn = n0 + tx * 8 + 2 * nj;
            unsigned long long v = acc[mi][nj];
            float lo = __int_as_float((int)(unsigned)v);
            float hi = __int_as_float((int)(v >> 32));
            lo = fmaxf(tanhf(lo + bias[cn]), 0.f);
            hi = fmaxf(tanhf(hi + bias[cn + 1]), 0.f);
            crow[cn] = lo;
            crow[cn + 1] = hi;
        }
    }
}

// ---------------- last layer GEMM (out_c = 3), tanh only, writes d_out ----------------
__global__ void __launch_bounds__(256) k_gemm_small(int K, const float* __restrict__ bias,
                                                    float* __restrict__ out) {
    int warp = blockIdx.x * 8 + (threadIdx.x >> 5);
    int lane = threadIdx.x & 31;
    if (warp >= NN) return;
    const float* a = &g_aggr[(size_t)warp * ALD];
    float c0 = 0.f, c1 = 0.f, c2 = 0.f;
    for (int k = lane; k < K; k += 32) {
        float v = a[k];
        c0 = fmaf(v, g_wperm[k], c0);
        c1 = fmaf(v, g_wperm[ALD + k], c1);
        c2 = fmaf(v, g_wperm[2 * ALD + k], c2);
    }
#pragma unroll
    for (int o = 16; o; o >>= 1) {
        c0 += __shfl_down_sync(0xffffffffu, c0, o);
        c1 += __shfl_down_sync(0xffffffffu, c1, o);
        c2 += __shfl_down_sync(0xffffffffu, c2, o);
    }
    if (lane == 0) {
        out[(size_t)warp * 3 + 0] = tanhf(c0 + bias[0]);
        out[(size_t)warp * 3 + 1] = tanhf(c1 + bias[1]);
        out[(size_t)warp * 3 + 2] = tanhf(c2 + bias[2]);
    }
}

// ---------------- launch ----------------
extern "C" void kernel_launch(void* const* d_in, const int* in_sizes, int n_in,
                              void* d_out, int out_size) {
    (void)in_sizes; (void)n_in; (void)out_size;
    const float* x   = (const float*)d_in[0];
    const float* sdf = (const float*)d_in[1];
    const float* nat = (const float*)d_in[2];
    const float* ea  = (const float*)d_in[3];
    const float* fy  = (const float*)d_in[4];
    const void*  ei  = d_in[5];
    const float* win[6];  const float* bin[6];
    const float* wout[6]; const float* bout[6];
    for (int l = 0; l < 6; l++) {
        win[l]  = (const float*)d_in[6 + 4 * l];
        bin[l]  = (const float*)d_in[7 + 4 * l];
        wout[l] = (const float*)d_in[8 + 4 * l];
        bout[l] = (const float*)d_in[9 + 4 * l];
    }
    float* out = (float*)d_out;

    static const int IN_C[6] = {7, 513, 513, 516, 513, 513};
    static const int COFF[6] = {0, 0, 3, 0, 0, 0};

    const int TB = 256;
    // CSR (dst is shared by all layers)
    k_detect<<<1, 1>>>((const int*)ei);
    k_zero<<<(NN + TB - 1) / TB, TB>>>();
    k_hist<<<(NE + TB - 1) / TB, TB>>>(ei);
    k_scan<<<1, 1024>>>();
    k_cursor<<<(NN + TB - 1) / TB, TB>>>();
    k_scatter<<<(NE + TB - 1) / TB, TB>>>(ei, ea);
    k_prep<<<(NN + TB - 1) / TB, TB>>>(x, sdf, nat);

    for (int l = 0; l < 6; l++) {
        const int inc = IN_C[l];
        const int K = 3 * inc;
        k_aggr<<<(NN + 63) / 64, 256>>>(inc, win[l], bin[l]);
        const int oc = (l < 5) ? 512 : 3;
        k_permw<<<(oc * K + TB - 1) / TB, TB>>>(wout[l], oc, inc);
        if (l < 5) {
            dim3 grid(4, (NN + 127) / 128);
            k_gemm<<<grid, 256>>>(NN, K, bout[l], COFF[l]);
        } else {
            k_gemm_small<<<(NN + 7) / 8, 256>>>(K, bout[l], out);
        }
        // rebuild concat columns for the next layer's xc
        if (l == 0) {                  // p1 input: [out512, attr]
            k_setcol<<<(NN + TB - 1) / TB, TB>>>(512, nat);
        } else if (l == 2) {           // c0 input: [fy(3), out512 @col3, attr @col515]
            k_copyfy<<<(NN * 3 + TB - 1) / TB, TB>>>(fy);
            k_setcol<<<(NN + TB - 1) / TB, TB>>>(515, nat);
        } else if (l == 3) {           // c1 input: [out512, attr] (col 512 was clobbered by c0's 516-wide input)
            k_setcol<<<(NN + TB - 1) / TB, TB>>>(512, nat);
        }
    }
}

// round 7
// speedup vs baseline: 1.9809x; 1.9809x over previous
#include <cuda_runtime.h>
#include <cuda_bf16.h>
#include <math.h>
#include <stdint.h>

#define NN 50000
#define NE 200000
#define XLD 516      // xc row stride (floats)
#define AP  1600     // bf16 A/B row stride (multiple of 32)

// ---------------- scratch ----------------
__device__ float g_xc[(size_t)NN * XLD];
__device__ __align__(16) __nv_bfloat16 g_ahi[(size_t)NN * AP];
__device__ __align__(16) __nv_bfloat16 g_alo[(size_t)NN * AP];
__device__ __align__(16) __nv_bfloat16 g_wbhi[(size_t)512 * AP];
__device__ __align__(16) __nv_bfloat16 g_wblo[(size_t)512 * AP];
__device__ int   g_cnt[NN];
__device__ int   g_rowptr[NN + 1];
__device__ int   g_cursor[NN];
__device__ int   g_src[NE];
__device__ float g_ea[NE * 6];
__device__ int   g_is64;

// ---------------- helpers ----------------
__device__ __forceinline__ uint32_t su32(const void* p) {
    uint32_t a;
    asm("{ .reg .u64 t; cvta.to.shared.u64 t, %1; cvt.u32.u64 %0, t; }" : "=r"(a) : "l"(p));
    return a;
}
__device__ __forceinline__ void ldm4(uint32_t* r, uint32_t addr) {
    asm volatile("ldmatrix.sync.aligned.m8n8.x4.shared.b16 {%0,%1,%2,%3}, [%4];"
                 : "=r"(r[0]), "=r"(r[1]), "=r"(r[2]), "=r"(r[3]) : "r"(addr));
}
__device__ __forceinline__ void mma16816(float* d, const uint32_t* a, const uint32_t* b) {
    asm volatile(
        "mma.sync.aligned.m16n8k16.row.col.f32.bf16.bf16.f32 "
        "{%0,%1,%2,%3}, {%4,%5,%6,%7}, {%8,%9}, {%0,%1,%2,%3};"
        : "+f"(d[0]), "+f"(d[1]), "+f"(d[2]), "+f"(d[3])
        : "r"(a[0]), "r"(a[1]), "r"(a[2]), "r"(a[3]), "r"(b[0]), "r"(b[1]));
}
__device__ __forceinline__ float ftanh(float x) {
    float e = __expf(2.0f * x);
    return 1.0f - __fdividef(2.0f, e + 1.0f);
}

// ---------------- edge_index dtype detection ----------------
__global__ void k_detect(const int* ei32) {
    if (threadIdx.x == 0 && blockIdx.x == 0) {
        int z = 1;
        for (int k = 0; k < 64; k++)
            if (ei32[2 * k + 1] != 0) { z = 0; break; }
        g_is64 = z;
    }
}
__device__ __forceinline__ int eload(const void* ei, int pos) {
    if (g_is64) return (int)((const long long*)ei)[pos];
    return ((const int*)ei)[pos];
}

// ---------------- CSR construction ----------------
__global__ void k_zero() {
    int i = blockIdx.x * blockDim.x + threadIdx.x;
    if (i < NN) g_cnt[i] = 0;
}
__global__ void k_hist(const void* ei) {
    int e = blockIdx.x * blockDim.x + threadIdx.x;
    if (e < NE) atomicAdd(&g_cnt[eload(ei, NE + e)], 1);
}
__global__ void k_scan() {
    __shared__ int sm[1024];
    const int CH = (NN + 1023) / 1024;
    int t = threadIdx.x;
    int base = t * CH;
    int s = 0;
    for (int j = 0; j < CH; j++) {
        int i = base + j;
        if (i < NN) s += g_cnt[i];
    }
    sm[t] = s;
    __syncthreads();
    for (int off = 1; off < 1024; off <<= 1) {
        int v = (t >= off) ? sm[t - off] : 0;
        __syncthreads();
        sm[t] += v;
        __syncthreads();
    }
    int run = sm[t] - s;
    for (int j = 0; j < CH; j++) {
        int i = base + j;
        if (i < NN) { g_rowptr[i] = run; run += g_cnt[i]; }
    }
    if (t == 1023) g_rowptr[NN] = sm[1023];
}
__global__ void k_cursor() {
    int i = blockIdx.x * blockDim.x + threadIdx.x;
    if (i < NN) g_cursor[i] = g_rowptr[i];
}
__global__ void k_scatter(const void* ei, const float* __restrict__ ea) {
    int e = blockIdx.x * blockDim.x + threadIdx.x;
    if (e >= NE) return;
    int d = eload(ei, NE + e);
    int s = eload(ei, e);
    int pos = atomicAdd(&g_cursor[d], 1);
    g_src[pos] = s;
#pragma unroll
    for (int a = 0; a < 6; a++) g_ea[pos * 6 + a] = ea[e * 6 + a];
}

// ---------------- xc preparation / fixups ----------------
__global__ void k_prep(const float* __restrict__ x, const float* __restrict__ sdf,
                       const float* __restrict__ nat) {
    int n = blockIdx.x * blockDim.x + threadIdx.x;
    if (n >= NN) return;
    float* r = &g_xc[(size_t)n * XLD];
#pragma unroll
    for (int c = 0; c < 5; c++) r[c] = x[n * 5 + c];
    r[5] = sdf[n];
    r[6] = nat[n];
}
__global__ void k_setcol(int col, const float* __restrict__ src) {
    int n = blockIdx.x * blockDim.x + threadIdx.x;
    if (n < NN) g_xc[(size_t)n * XLD + col] = src[n];
}
__global__ void k_copyfy(const float* __restrict__ fy) {
    int idx = blockIdx.x * blockDim.x + threadIdx.x;
    if (idx >= NN * 3) return;
    int n = idx / 3, c = idx - n * 3;
    g_xc[(size_t)n * XLD + c] = fy[idx];
}

// ---------------- weight prep: bf16 hi/lo split, permuted k = h*in_c + i ----------------
__global__ void k_permw_bf16(const float* __restrict__ wout, int in_c, int Kpad) {
    int K = 3 * in_c;
    int idx = blockIdx.x * blockDim.x + threadIdx.x;
    if (idx >= 512 * Kpad) return;
    int o = idx / Kpad, k = idx - o * Kpad;
    float v = 0.f;
    if (k < K) {
        int h = k / in_c, i = k - h * in_c;
        v = wout[(size_t)o * K + i * 3 + h];
    }
    __nv_bfloat16 hi = __float2bfloat16(v);
    __nv_bfloat16 lo = __float2bfloat16(v - __bfloat162float(hi));
    g_wbhi[(size_t)o * AP + k] = hi;
    g_wblo[(size_t)o * AP + k] = lo;
}

// ---------------- zero-pad A columns [K, Kpad) ----------------
__global__ void k_padA(int K, int Kpad) {
    int pad = Kpad - K;
    int idx = blockIdx.x * blockDim.x + threadIdx.x;
    if (idx >= NN * pad) return;
    int n = idx / pad, c = K + idx - n * pad;
    g_ahi[(size_t)n * AP + c] = __float2bfloat16(0.f);
    g_alo[(size_t)n * AP + c] = __float2bfloat16(0.f);
}

// ---------------- fused scaling + gather + segment-sum -> bf16 hi/lo ----------------
__global__ void __launch_bounds__(256) k_aggr(int in_c, const float* __restrict__ win,
                                              const float* __restrict__ bin) {
    __shared__ float s_w[1548 * 6];
    __shared__ float s_b[1548];
    int R = 3 * in_c;
    for (int t = threadIdx.x; t < R * 6; t += 256) s_w[t] = win[t];
    for (int t = threadIdx.x; t < R;     t += 256) s_b[t] = bin[t];
    __syncthreads();

    int n0 = blockIdx.x * 64;
    int nend = (n0 + 64 < NN) ? n0 + 64 : NN;
    for (int n = n0; n < nend; n++) {
        int rs = g_rowptr[n], re = g_rowptr[n + 1];
        for (int i = threadIdx.x; i < in_c; i += 256) {
            const float* w = &s_w[i * 18];
            float b0 = s_b[3 * i + 0], b1 = s_b[3 * i + 1], b2 = s_b[3 * i + 2];
            float a0 = 0.f, a1 = 0.f, a2 = 0.f;
            for (int j = rs; j < re; j++) {
                int s = g_src[j];
                float xv = __ldg(&g_xc[(size_t)s * XLD + i]);
                const float* eap = &g_ea[j * 6];
                float s0 = b0, s1 = b1, s2 = b2;
#pragma unroll
                for (int a = 0; a < 6; a++) {
                    float e = eap[a];
                    s0 = fmaf(e, w[a],      s0);
                    s1 = fmaf(e, w[6 + a],  s1);
                    s2 = fmaf(e, w[12 + a], s2);
                }
                a0 = fmaf(fmaxf(s0, 0.f), xv, a0);
                a1 = fmaf(fmaxf(s1, 0.f), xv, a1);
                a2 = fmaf(fmaxf(s2, 0.f), xv, a2);
            }
            size_t rb = (size_t)n * AP;
            __nv_bfloat16 h;
            h = __float2bfloat16(a0);
            g_ahi[rb + i] = h;
            g_alo[rb + i] = __float2bfloat16(a0 - __bfloat162float(h));
            h = __float2bfloat16(a1);
            g_ahi[rb + in_c + i] = h;
            g_alo[rb + in_c + i] = __float2bfloat16(a1 - __bfloat162float(h));
            h = __float2bfloat16(a2);
            g_ahi[rb + 2 * in_c + i] = h;
            g_alo[rb + 2 * in_c + i] = __float2bfloat16(a2 - __bfloat162float(h));
        }
    }
}

// ---------------- HMMA split-bf16 GEMM ----------------
// CTA tile 128x64, warp tile 32x32, K chunks of 32 bf16.
// D = Ahi*Bhi + Ahi*Blo + Alo*Bhi (fp32 accum)
// epilogue: g_xc[m, coloff+n] = relu(tanh(D + bias[n]))  (scalar stores: coloff may be odd)
#define SROW 80                 // padded smem row stride (bytes), conflict-free
#define SA_HI 0
#define SA_LO (128 * SROW)      // 10240
#define SB_HI (2 * 128 * SROW)  // 20480
#define SB_LO (SB_HI + 64 * SROW)
#define SM_SZ (SB_LO + 64 * SROW)   // 30720

__global__ void __launch_bounds__(256, 2) k_gemm_mma(int M, int NC,
                                                     const float* __restrict__ bias,
                                                     int coloff) {
    __shared__ __align__(16) char smem[SM_SZ];
    const int tid = threadIdx.x;
    const int wid = tid >> 5;
    const int lane = tid & 31;
    const int m0 = blockIdx.y * 128;
    const int n0 = blockIdx.x * 64;
    const uint32_t sb = su32(smem);

    const int wm = (wid & 3) * 32;       // warp m offset within tile
    const int wn = (wid >> 2) * 32;      // warp n offset within tile

    float acc[2][4][4];
#pragma unroll
    for (int mt = 0; mt < 2; mt++)
#pragma unroll
        for (int nt = 0; nt < 4; nt++)
#pragma unroll
            for (int q = 0; q < 4; q++) acc[mt][nt][q] = 0.f;

    // per-thread global-load coordinates
    const int ar0 = tid >> 2, ac0 = tid & 3;           // A part 1: rows 0..63
    const int ar1 = (tid + 256) >> 2, ac1 = tid & 3;   // A part 2: rows 64..127
    const int br = tid >> 2, bc = tid & 3;             // B: rows 0..63
    int rga0 = m0 + ar0; if (rga0 >= M) rga0 = M - 1;
    int rga1 = m0 + ar1; if (rga1 >= M) rga1 = M - 1;

    uint4 pah0, pah1, pal0, pal1, pbh, pbl;
    {
        size_t o0 = (size_t)rga0 * AP + ac0 * 8;
        size_t o1 = (size_t)rga1 * AP + ac1 * 8;
        size_t ob = (size_t)(n0 + br) * AP + bc * 8;
        pah0 = *(const uint4*)(g_ahi + o0);
        pah1 = *(const uint4*)(g_ahi + o1);
        pal0 = *(const uint4*)(g_alo + o0);
        pal1 = *(const uint4*)(g_alo + o1);
        pbh  = *(const uint4*)(g_wbhi + ob);
        pbl  = *(const uint4*)(g_wblo + ob);
    }

    for (int c = 0; c < NC; c++) {
        // stage to smem
        *(uint4*)(smem + SA_HI + ar0 * SROW + ac0 * 16) = pah0;
        *(uint4*)(smem + SA_HI + ar1 * SROW + ac1 * 16) = pah1;
        *(uint4*)(smem + SA_LO + ar0 * SROW + ac0 * 16) = pal0;
        *(uint4*)(smem + SA_LO + ar1 * SROW + ac1 * 16) = pal1;
        *(uint4*)(smem + SB_HI + br * SROW + bc * 16) = pbh;
        *(uint4*)(smem + SB_LO + br * SROW + bc * 16) = pbl;
        __syncthreads();

        if (c + 1 < NC) {
            int kb = (c + 1) * 32;
            size_t o0 = (size_t)rga0 * AP + kb + ac0 * 8;
            size_t o1 = (size_t)rga1 * AP + kb + ac1 * 8;
            size_t ob = (size_t)(n0 + br) * AP + kb + bc * 8;
            pah0 = *(const uint4*)(g_ahi + o0);
            pah1 = *(const uint4*)(g_ahi + o1);
            pal0 = *(const uint4*)(g_alo + o0);
            pal1 = *(const uint4*)(g_alo + o1);
            pbh  = *(const uint4*)(g_wbhi + ob);
            pbl  = *(const uint4*)(g_wblo + ob);
        }

#pragma unroll
        for (int s = 0; s < 2; s++) {
            uint32_t ah[2][4], al[2][4];
#pragma unroll
            for (int mt = 0; mt < 2; mt++) {
                uint32_t row = wm + mt * 16 + (lane & 15);
                uint32_t ad = sb + SA_HI + row * SROW + s * 32 + (lane >> 4) * 16;
                ldm4(ah[mt], ad);
                ldm4(al[mt], ad + (SA_LO - SA_HI));
            }
            uint32_t bh[4][2], bl[4][2];
#pragma unroll
            for (int p = 0; p < 2; p++) {
                uint32_t row = wn + p * 16 + (lane & 7) + (lane >> 4) * 8;
                uint32_t bd = sb + SB_HI + row * SROW + s * 32 + ((lane >> 3) & 1) * 16;
                uint32_t r[4];
                ldm4(r, bd);
                bh[2 * p][0] = r[0]; bh[2 * p][1] = r[1];
                bh[2 * p + 1][0] = r[2]; bh[2 * p + 1][1] = r[3];
                ldm4(r, bd + (SB_LO - SB_HI));
                bl[2 * p][0] = r[0]; bl[2 * p][1] = r[1];
                bl[2 * p + 1][0] = r[2]; bl[2 * p + 1][1] = r[3];
            }
#pragma unroll
            for (int mt = 0; mt < 2; mt++)
#pragma unroll
                for (int nt = 0; nt < 4; nt++) {
                    mma16816(acc[mt][nt], ah[mt], bh[nt]);
                    mma16816(acc[mt][nt], ah[mt], bl[nt]);
                    mma16816(acc[mt][nt], al[mt], bh[nt]);
                }
        }
        __syncthreads();
    }

    // epilogue (scalar stores — coloff may make addresses 4B-aligned only)
#pragma unroll
    for (int mt = 0; mt < 2; mt++) {
        int gm0 = m0 + wm + mt * 16 + (lane >> 2);
        int gm1 = gm0 + 8;
#pragma unroll
        for (int nt = 0; nt < 4; nt++) {
            int cn = n0 + wn + nt * 8 + (lane & 3) * 2;
            float b0 = bias[cn], b1 = bias[cn + 1];
            if (gm0 < M) {
                float* p = &g_xc[(size_t)gm0 * XLD + coloff + cn];
                p[0] = fmaxf(ftanh(acc[mt][nt][0] + b0), 0.f);
                p[1] = fmaxf(ftanh(acc[mt][nt][1] + b1), 0.f);
            }
            if (gm1 < M) {
                float* p = &g_xc[(size_t)gm1 * XLD + coloff + cn];
                p[0] = fmaxf(ftanh(acc[mt][nt][2] + b0), 0.f);
                p[1] = fmaxf(ftanh(acc[mt][nt][3] + b1), 0.f);
            }
        }
    }
}

// ---------------- last layer (out_c = 3): warp per node, fp32, tanh only ----------------
__global__ void __launch_bounds__(256) k_gemm_small(int in_c, const float* __restrict__ wout,
                                                    const float* __restrict__ bias,
                                                    float* __restrict__ out) {
    int node = blockIdx.x * 8 + (threadIdx.x >> 5);
    int lane = threadIdx.x & 31;
    if (node >= NN) return;
    const int K = 3 * in_c;
    const __nv_bfloat16* hi = g_ahi + (size_t)node * AP;
    const __nv_bfloat16* lo = g_alo + (size_t)node * AP;
    float c0 = 0.f, c1 = 0.f, c2 = 0.f;
    for (int h = 0; h < 3; h++) {
        for (int i = lane; i < in_c; i += 32) {
            int k = h * in_c + i;
            float a = __bfloat162float(hi[k]) + __bfloat162float(lo[k]);
            int wi = i * 3 + h;
            c0 = fmaf(a, wout[0 * (size_t)K + wi], c0);
            c1 = fmaf(a, wout[1 * (size_t)K + wi], c1);
            c2 = fmaf(a, wout[2 * (size_t)K + wi], c2);
        }
    }
#pragma unroll
    for (int o = 16; o; o >>= 1) {
        c0 += __shfl_down_sync(0xffffffffu, c0, o);
        c1 += __shfl_down_sync(0xffffffffu, c1, o);
        c2 += __shfl_down_sync(0xffffffffu, c2, o);
    }
    if (lane == 0) {
        out[(size_t)node * 3 + 0] = tanhf(c0 + bias[0]);
        out[(size_t)node * 3 + 1] = tanhf(c1 + bias[1]);
        out[(size_t)node * 3 + 2] = tanhf(c2 + bias[2]);
    }
}

// ---------------- launch ----------------
extern "C" void kernel_launch(void* const* d_in, const int* in_sizes, int n_in,
                              void* d_out, int out_size) {
    (void)in_sizes; (void)n_in; (void)out_size;
    const float* x   = (const float*)d_in[0];
    const float* sdf = (const float*)d_in[1];
    const float* nat = (const float*)d_in[2];
    const float* ea  = (const float*)d_in[3];
    const float* fy  = (const float*)d_in[4];
    const void*  ei  = d_in[5];
    const float* win[6];  const float* bin[6];
    const float* wout[6]; const float* bout[6];
    for (int l = 0; l < 6; l++) {
        win[l]  = (const float*)d_in[6 + 4 * l];
        bin[l]  = (const float*)d_in[7 + 4 * l];
        wout[l] = (const float*)d_in[8 + 4 * l];
        bout[l] = (const float*)d_in[9 + 4 * l];
    }
    float* out = (float*)d_out;

    static const int IN_C[6] = {7, 513, 513, 516, 513, 513};
    static const int COFF[6] = {0, 0, 3, 0, 0, 0};

    const int TB = 256;
    k_detect<<<1, 1>>>((const int*)ei);
    k_zero<<<(NN + TB - 1) / TB, TB>>>();
    k_hist<<<(NE + TB - 1) / TB, TB>>>(ei);
    k_scan<<<1, 1024>>>();
    k_cursor<<<(NN + TB - 1) / TB, TB>>>();
    k_scatter<<<(NE + TB - 1) / TB, TB>>>(ei, ea);
    k_prep<<<(NN + TB - 1) / TB, TB>>>(x, sdf, nat);

    for (int l = 0; l < 6; l++) {
        const int inc = IN_C[l];
        const int K = 3 * inc;
        const int NC = (K + 31) / 32;
        const int Kpad = NC * 32;

        k_aggr<<<(NN + 63) / 64, 256>>>(inc, win[l], bin[l]);
        {
            int padn = Kpad - K;
            if (padn > 0)
                k_padA<<<(NN * padn + TB - 1) / TB, TB>>>(K, Kpad);
        }
        if (l < 5) {
            k_permw_bf16<<<(512 * Kpad + TB - 1) / TB, TB>>>(wout[l], inc, Kpad);
            dim3 grid(8, (NN + 127) / 128);   // x = n-block (fast) for A reuse in L2
            k_gemm_mma<<<grid, 256>>>(NN, NC, bout[l], COFF[l]);
        } else {
            k_gemm_small<<<(NN + 7) / 8, 256>>>(inc, wout[l], bout[l], out);
        }
        if (l == 0) {
            k_setcol<<<(NN + TB - 1) / TB, TB>>>(512, nat);
        } else if (l == 2) {
            k_copyfy<<<(NN * 3 + TB - 1) / TB, TB>>>(fy);
            k_setcol<<<(NN + TB - 1) / TB, TB>>>(515, nat);
        } else if (l == 3) {
            k_setcol<<<(NN + TB - 1) / TB, TB>>>(512, nat);
        }
    }
}